// round 5
// baseline (speedup 1.0000x reference)
#include <cuda_runtime.h>

// Cubic Bezier spline evaluation — grid-stride software-pipelined, packed f32x2.
//   d_in[0]: t              float32 [N]      (sorted, in [0,1))
//   d_in[1]: control_points float32 [S*2, 2]
//   d_in[2]: joint_points   float32 [S+1, 2]
// Output: float32 [N, 2]

struct __align__(8) F2 { float x, y; };
typedef unsigned long long u64;

__device__ __forceinline__ u64 pack2(float lo, float hi) {
    u64 r; asm("mov.b64 %0, {%1, %2};" : "=l"(r) : "f"(lo), "f"(hi)); return r;
}
__device__ __forceinline__ u64 fma2(u64 a, u64 b, u64 c) {
    u64 d; asm("fma.rn.f32x2 %0, %1, %2, %3;" : "=l"(d) : "l"(a), "l"(b), "l"(c));
    return d;
}

// Packed power-basis coefficients for one segment: each u64 = (x, y) fp32 pair.
struct CoeffsP { u64 c0, c1, c2, c3; };

__device__ __forceinline__ CoeffsP make_coeffs(int seg,
                                               const float4* __restrict__ ctrl4,
                                               const F2* __restrict__ joint) {
    F2 P0 = joint[seg];
    F2 P3 = joint[seg + 1];
    float4 cc = ctrl4[seg];          // (P1.x, P1.y, P2.x, P2.y)

    CoeffsP c;
    c.c0 = pack2(P0.x, P0.y);
    c.c1 = pack2(3.0f * (cc.x - P0.x),
                 3.0f * (cc.y - P0.y));
    c.c2 = pack2(3.0f * (P0.x - 2.0f * cc.x + cc.z),
                 3.0f * (P0.y - 2.0f * cc.y + cc.w));
    c.c3 = pack2(fmaf(3.0f, cc.x - cc.z, P3.x - P0.x),
                 fmaf(3.0f, cc.y - cc.w, P3.y - P0.y));
    return c;
}

__device__ __forceinline__ u64 eval_packed(const CoeffsP& c, float lt) {
    u64 ltp = pack2(lt, lt);
    u64 acc = fma2(c.c3, ltp, c.c2);
    acc     = fma2(acc,  ltp, c.c1);
    acc     = fma2(acc,  ltp, c.c0);
    return acc;                       // == (x, y) output pair
}

__device__ __forceinline__ void process_group(float4 a, float4 b,
                                              const float4* __restrict__ ctrl4,
                                              const F2* __restrict__ joint,
                                              u64* __restrict__ outp,  // &out[2*base] as u64*
                                              int S, float Sf)
{
    float tv[8] = {a.x, a.y, a.z, a.w, b.x, b.y, b.z, b.w};
    int   seg[8];
    float lt[8];
    #pragma unroll
    for (int k = 0; k < 8; ++k) {
        float u  = tv[k] * Sf;
        float fs = floorf(u);
        int   s  = (int)fs;
        float l  = u - fs;
        if (s >= S) { s = S - 1; l = 1.0f; }
        seg[k] = s; lt[k] = l;
    }

    u64 r[8];
    if (seg[0] == seg[7]) {
        // Fast path: all 8 samples share one segment (~99.6% of groups).
        CoeffsP c = make_coeffs(seg[0], ctrl4, joint);
        #pragma unroll
        for (int k = 0; k < 8; ++k) r[k] = eval_packed(c, lt[k]);
    } else {
        #pragma unroll
        for (int k = 0; k < 8; ++k) {
            CoeffsP c = make_coeffs(seg[k], ctrl4, joint);
            r[k] = eval_packed(c, lt[k]);
        }
    }

    ulonglong2* o = reinterpret_cast<ulonglong2*>(outp);
    o[0] = make_ulonglong2(r[0], r[1]);
    o[1] = make_ulonglong2(r[2], r[3]);
    o[2] = make_ulonglong2(r[4], r[5]);
    o[3] = make_ulonglong2(r[6], r[7]);
}

__global__ void __launch_bounds__(256, 6)
spline_kernel(const float* __restrict__ t,
              const float4* __restrict__ ctrl4,
              const F2* __restrict__ joint,
              float* __restrict__ out,
              int n, int S, float Sf)
{
    int gid    = blockIdx.x * blockDim.x + threadIdx.x;
    int stride = gridDim.x * blockDim.x;
    int nGroups = n >> 3;             // groups of 8 samples

    // Software pipeline: prefetch next iteration's t before processing current.
    int g = gid;
    if (g < nGroups) {
        float4 a = *reinterpret_cast<const float4*>(t + 8 * g);
        float4 b = *reinterpret_cast<const float4*>(t + 8 * g + 4);
        while (true) {
            int gn = g + stride;
            float4 an, bn;
            bool more = (gn < nGroups);
            if (more) {
                an = *reinterpret_cast<const float4*>(t + 8 * gn);
                bn = *reinterpret_cast<const float4*>(t + 8 * gn + 4);
            }
            process_group(a, b, ctrl4, joint,
                          reinterpret_cast<u64*>(out + 16 * (long long)g), S, Sf);
            if (!more) break;
            g = gn; a = an; b = bn;
        }
    }

    // Tail (n % 8 samples), handled by one thread.
    if (gid == 0) {
        for (int k = nGroups * 8; k < n; ++k) {
            float u  = t[k] * Sf;
            float fs = floorf(u);
            int   s  = (int)fs;
            float l  = u - fs;
            if (s >= S) { s = S - 1; l = 1.0f; }
            CoeffsP c = make_coeffs(s, ctrl4, joint);
            u64 r = eval_packed(c, l);
            reinterpret_cast<u64*>(out)[k] = r;
        }
    }
}

extern "C" void kernel_launch(void* const* d_in, const int* in_sizes, int n_in,
                              void* d_out, int out_size)
{
    const float*  t     = (const float*)d_in[0];
    const float4* ctrl4 = (const float4*)d_in[1];
    const F2*     joint = (const F2*)d_in[2];
    float*        out   = (float*)d_out;

    int n = in_sizes[0];
    int S = in_sizes[2] / 2 - 1;       // joint_points has (S+1)*2 floats
    float Sf = (float)S;

    int threads = 256;
    int blocks  = 148 * 8;             // ~3.5 groups per thread at N=8.4M
    int maxBlocks = (n / 8 + threads - 1) / threads;
    if (maxBlocks < 1) maxBlocks = 1;
    if (blocks > maxBlocks) blocks = maxBlocks;
    spline_kernel<<<blocks, threads>>>(t, ctrl4, joint, out, n, S, Sf);
}